// round 10
// baseline (speedup 1.0000x reference)
#include <cuda_runtime.h>
#include <math.h>
#include <stdint.h>

// Problem dims
#define BB 2
#define SS 2048
#define DD 1024
#define HH 16
#define DKK 64
#define DFF 4096
#define NROW 4096   // B*S

// ---------------- scratch (device globals; no allocation allowed) ----------------
__device__ float g_xn [NROW * DD];
__device__ float g_q  [NROW * DD];
__device__ float g_k  [NROW * DD];
__device__ float g_v  [NROW * DD];
__device__ float g_ctx[NROW * DD];
__device__ float g_x1 [NROW * DD];
__device__ float g_h  [NROW * DFF];

// ---------------- LayerNorm (unbiased std, eps added to std) ----------------
__global__ __launch_bounds__(256)
void ln_kernel(const float* __restrict__ x, const float* __restrict__ alpha,
               const float* __restrict__ beta, float* __restrict__ y) {
    __shared__ float red[8];
    int row = blockIdx.x;
    int tid = threadIdx.x;
    const float* xr = x + (size_t)row * DD;
    float4 v = *(const float4*)(xr + tid * 4);
    float s = v.x + v.y + v.z + v.w;
    #pragma unroll
    for (int off = 16; off > 0; off >>= 1) s += __shfl_xor_sync(0xffffffffu, s, off);
    if ((tid & 31) == 0) red[tid >> 5] = s;
    __syncthreads();
    float tot = red[0] + red[1] + red[2] + red[3] + red[4] + red[5] + red[6] + red[7];
    float mean = tot * (1.0f / 1024.0f);
    float dx = v.x - mean, dy = v.y - mean, dz = v.z - mean, dw = v.w - mean;
    float sq = dx * dx + dy * dy + dz * dz + dw * dw;
    #pragma unroll
    for (int off = 16; off > 0; off >>= 1) sq += __shfl_xor_sync(0xffffffffu, sq, off);
    __syncthreads();
    if ((tid & 31) == 0) red[tid >> 5] = sq;
    __syncthreads();
    float var = (red[0] + red[1] + red[2] + red[3] + red[4] + red[5] + red[6] + red[7])
                * (1.0f / 1023.0f);            // ddof=1 (unbiased, torch default)
    float sc = alpha[0] / (sqrtf(var) + 1e-6f); // eps added to std, not var
    float be = beta[0];
    float4 o = make_float4(dx * sc + be, dy * sc + be, dz * sc + be, dw * sc + be);
    *(float4*)(y + (size_t)row * DD + tid * 4) = o;
}

// ---------------- TF32 helpers ----------------
__device__ __forceinline__ uint32_t f2tf(float f) {
    uint32_t u;
    asm("cvt.rna.tf32.f32 %0, %1;" : "=r"(u) : "f"(f));
    return u;
}

#define MMA_TF32(d, a, b) \
    asm volatile("mma.sync.aligned.m16n8k8.row.col.f32.tf32.tf32.f32 " \
                 "{%0,%1,%2,%3},{%4,%5,%6,%7},{%8,%9},{%0,%1,%2,%3};" \
                 : "+f"(d[0]), "+f"(d[1]), "+f"(d[2]), "+f"(d[3]) \
                 : "r"(a[0]), "r"(a[1]), "r"(a[2]), "r"(a[3]), "r"(b[0]), "r"(b[1]))

// ---------------- TF32 tensor-core GEMM body, 128x128 tile, kt=32, 2-stage smem ----------------
// EPI: 0 = bias + scatter to [B,H,S,DK]; 1 = bias + residual add; 2 = bias + ReLU
#define AS_STRIDE 36    // frag-load bank = 4*(lane>>2)+(lane&3), conflict-free
#define BS_STRIDE 136   // frag-load bank = 8*(lane&3)+(lane>>2), conflict-free
#define A_WORDS (128 * AS_STRIDE)            // 4608
#define B_WORDS (32 * BS_STRIDE)             // 4352
#define STAGE_WORDS (A_WORDS + B_WORDS)      // 8960
#define GEMM_SMEM_BYTES (2 * STAGE_WORDS * 4)  // 71680

template <int EPI>
__device__ __forceinline__
void gemm_body(const float* __restrict__ A, const float* __restrict__ Bm,
               const float* __restrict__ bias, const float* __restrict__ res,
               float* __restrict__ C, int N, int K, int brow, int bcol,
               uint32_t* smem) {
    uint32_t* AsBuf[2] = { smem, smem + STAGE_WORDS };
    uint32_t* BsBuf[2] = { smem + A_WORDS, smem + STAGE_WORDS + A_WORDS };

    int tid  = threadIdx.x;
    int lane = tid & 31;
    int wid  = tid >> 5;

    int wm = (wid >> 2) * 64;   // warp m base: 0 / 64
    int wn = (wid & 3) * 32;    // warp n base: 0/32/64/96
    int gr = lane >> 2;         // 0..7
    int gk = lane & 3;          // 0..3

    int am[4], ac[4], bk[4], bn[4];
    #pragma unroll
    for (int i = 0; i < 4; i++) {
        int idx = tid + i * 256;
        am[i] = idx >> 3;  ac[i] = (idx & 7) << 2;    // A tile 128x32
        bk[i] = idx >> 5;  bn[i] = (idx & 31) << 2;   // B tile 32x128
    }
    const float* Abase = A + (size_t)brow * K;
    const float* Bbase = Bm + bcol;

    float4 pa[4], pb[4];
    // tile 0 -> stage 0
    #pragma unroll
    for (int i = 0; i < 4; i++) {
        pa[i] = *(const float4*)(Abase + (size_t)am[i] * K + ac[i]);
        pb[i] = *(const float4*)(Bbase + (size_t)bk[i] * N + bn[i]);
    }
    #pragma unroll
    for (int i = 0; i < 4; i++) {
        uint4 ua = make_uint4(f2tf(pa[i].x), f2tf(pa[i].y), f2tf(pa[i].z), f2tf(pa[i].w));
        uint4 ub = make_uint4(f2tf(pb[i].x), f2tf(pb[i].y), f2tf(pb[i].z), f2tf(pb[i].w));
        *(uint4*)&AsBuf[0][am[i] * AS_STRIDE + ac[i]] = ua;
        *(uint4*)&BsBuf[0][bk[i] * BS_STRIDE + bn[i]] = ub;
    }
    __syncthreads();

    int ntiles = K >> 5;
    // prefetch tile 1 into registers
    if (ntiles > 1) {
        #pragma unroll
        for (int i = 0; i < 4; i++) {
            pa[i] = *(const float4*)(Abase + (size_t)am[i] * K + 32 + ac[i]);
            pb[i] = *(const float4*)(Bbase + ((size_t)32 + bk[i]) * N + bn[i]);
        }
    }

    float acc[4][4][4];
    #pragma unroll
    for (int mt = 0; mt < 4; mt++)
        #pragma unroll
        for (int nt = 0; nt < 4; nt++)
            #pragma unroll
            for (int r = 0; r < 4; r++) acc[mt][nt][r] = 0.0f;

    for (int kt = 0; kt < ntiles; kt++) {
        int cur = kt & 1;
        const uint32_t* As = AsBuf[cur];
        const uint32_t* Bs = BsBuf[cur];
        // compute on current stage
        #pragma unroll
        for (int k8 = 0; k8 < 4; k8++) {
            int kb = k8 * 8;
            uint32_t a[4][4], b[4][2];
            #pragma unroll
            for (int mt = 0; mt < 4; mt++) {
                int r = wm + mt * 16 + gr;
                a[mt][0] = As[r * AS_STRIDE + kb + gk];
                a[mt][1] = As[(r + 8) * AS_STRIDE + kb + gk];
                a[mt][2] = As[r * AS_STRIDE + kb + gk + 4];
                a[mt][3] = As[(r + 8) * AS_STRIDE + kb + gk + 4];
            }
            #pragma unroll
            for (int nt = 0; nt < 4; nt++) {
                int cn = wn + nt * 8 + gr;
                b[nt][0] = Bs[(kb + gk) * BS_STRIDE + cn];
                b[nt][1] = Bs[(kb + gk + 4) * BS_STRIDE + cn];
            }
            #pragma unroll
            for (int mt = 0; mt < 4; mt++)
                #pragma unroll
                for (int nt = 0; nt < 4; nt++)
                    MMA_TF32(acc[mt][nt], a[mt], b[nt]);
        }
        // store tile kt+1 into the other stage (no conflict with reads of cur)
        if (kt + 1 < ntiles) {
            uint32_t* An = AsBuf[cur ^ 1];
            uint32_t* Bn = BsBuf[cur ^ 1];
            #pragma unroll
            for (int i = 0; i < 4; i++) {
                uint4 ua = make_uint4(f2tf(pa[i].x), f2tf(pa[i].y), f2tf(pa[i].z), f2tf(pa[i].w));
                uint4 ub = make_uint4(f2tf(pb[i].x), f2tf(pb[i].y), f2tf(pb[i].z), f2tf(pb[i].w));
                *(uint4*)&An[am[i] * AS_STRIDE + ac[i]] = ua;
                *(uint4*)&Bn[bk[i] * BS_STRIDE + bn[i]] = ub;
            }
        }
        __syncthreads();   // single barrier per k-tile
        // global prefetch for tile kt+2
        if (kt + 2 < ntiles) {
            #pragma unroll
            for (int i = 0; i < 4; i++) {
                pa[i] = *(const float4*)(Abase + (size_t)am[i] * K + (kt + 2) * 32 + ac[i]);
                pb[i] = *(const float4*)(Bbase + ((size_t)(kt + 2) * 32 + bk[i]) * N + bn[i]);
            }
        }
    }

    #pragma unroll
    for (int mt = 0; mt < 4; mt++) {
        int r0 = brow + wm + mt * 16 + gr;
        int r1 = r0 + 8;
        #pragma unroll
        for (int nt = 0; nt < 4; nt++) {
            int c = bcol + wn + nt * 8 + (gk << 1);
            float2 bv = *(const float2*)(bias + c);
            float2 lo = make_float2(acc[mt][nt][0] + bv.x, acc[mt][nt][1] + bv.y);
            float2 hi = make_float2(acc[mt][nt][2] + bv.x, acc[mt][nt][3] + bv.y);
            if (EPI == 1) {
                float2 rl = *(const float2*)(res + (size_t)r0 * N + c);
                float2 rh = *(const float2*)(res + (size_t)r1 * N + c);
                lo.x += rl.x; lo.y += rl.y; hi.x += rh.x; hi.y += rh.y;
            }
            if (EPI == 2) {
                lo.x = fmaxf(lo.x, 0.0f); lo.y = fmaxf(lo.y, 0.0f);
                hi.x = fmaxf(hi.x, 0.0f); hi.y = fmaxf(hi.y, 0.0f);
            }
            if (EPI == 0) {
                int h_ = c >> 6, dkc = c & 63;
                int b0_ = r0 >> 11, s0_ = r0 & 2047;
                int b1_ = r1 >> 11, s1_ = r1 & 2047;
                *(float2*)(C + ((((size_t)b0_ * HH + h_) * SS + s0_) << 6) + dkc) = lo;
                *(float2*)(C + ((((size_t)b1_ * HH + h_) * SS + s1_) << 6) + dkc) = hi;
            } else {
                *(float2*)(C + (size_t)r0 * N + c) = lo;
                *(float2*)(C + (size_t)r1 * N + c) = hi;
            }
        }
    }
}

template <int EPI>
__global__ __launch_bounds__(256)
void gemm_tc(const float* __restrict__ A, const float* __restrict__ Bm,
             const float* __restrict__ bias, const float* __restrict__ res,
             float* __restrict__ C, int N, int K) {
    extern __shared__ uint32_t smem_dyn[];
    gemm_body<EPI>(A, Bm, bias, res, C, N, K, blockIdx.y * 128, blockIdx.x * 128, smem_dyn);
}

// fused QKV: gridDim.z selects weight/bias/output
__global__ __launch_bounds__(256)
void gemm_qkv(const float* __restrict__ A,
              const float* __restrict__ W0, const float* __restrict__ W1q, const float* __restrict__ W2q,
              const float* __restrict__ c0, const float* __restrict__ c1, const float* __restrict__ c2,
              float* __restrict__ O0, float* __restrict__ O1, float* __restrict__ O2) {
    extern __shared__ uint32_t smem_dyn[];
    int z = blockIdx.z;
    const float* W = (z == 0) ? W0 : (z == 1) ? W1q : W2q;
    const float* bb = (z == 0) ? c0 : (z == 1) ? c1 : c2;
    float* O = (z == 0) ? O0 : (z == 1) ? O1 : O2;
    gemm_body<0>(A, W, bb, nullptr, O, DD, DD, blockIdx.y * 128, blockIdx.x * 128, smem_dyn);
}

// ---------------- TF32 tensor-core flash attention ----------------
// grid (S/64, B*H), 128 threads (4 warps), each warp m16 x n64 of a 64x64 tile.
#define ATT_ST 68   // 64 + 4 pad: fragment LDS bank = lane -> conflict-free

__global__ __launch_bounds__(128)
void attn_tc(const float* __restrict__ q, const float* __restrict__ k,
             const float* __restrict__ v, const int* __restrict__ mask,
             float* __restrict__ ctx) {
    __shared__ uint32_t KVs[64 * ATT_ST];  // K natural [kv][dk], then V transposed [dk][kv]
    __shared__ uint32_t Ps[64 * ATT_ST];   // P tf32 [qrow][kv]

    int tid  = threadIdx.x;
    int lane = tid & 31;
    int wid  = tid >> 5;     // 0..3
    int gr   = lane >> 2;    // 0..7
    int gk   = lane & 3;     // 0..3
    int wm   = wid * 16;

    int bh = blockIdx.y;
    int qt = blockIdx.x;
    int b  = bh >> 4;
    const float* qbase = q + ((size_t)bh * SS + qt * 64) * DKK;
    const float* kbase = k + (size_t)bh * SS * DKK;
    const float* vbase = v + (size_t)bh * SS * DKK;
    const int*   mbase = mask + b * SS;

    uint32_t qf[8][4];
    #pragma unroll
    for (int ks = 0; ks < 8; ks++) {
        int kc = ks * 8 + gk;
        qf[ks][0] = f2tf(0.125f * qbase[(wm + gr) * 64 + kc]);
        qf[ks][1] = f2tf(0.125f * qbase[(wm + gr + 8) * 64 + kc]);
        qf[ks][2] = f2tf(0.125f * qbase[(wm + gr) * 64 + kc + 4]);
        qf[ks][3] = f2tf(0.125f * qbase[(wm + gr + 8) * 64 + kc + 4]);
    }

    float o[8][4];
    #pragma unroll
    for (int nt = 0; nt < 8; nt++)
        #pragma unroll
        for (int r = 0; r < 4; r++) o[nt][r] = 0.0f;
    float m_lo = -1e30f, m_hi = -1e30f, l_lo = 0.0f, l_hi = 0.0f;

    for (int kt = 0; kt < SS / 64; kt++) {
        __syncthreads();
        #pragma unroll
        for (int i = 0; i < 8; i++) {
            int f = tid + i * 128;
            int r = f >> 4;
            int c = (f & 15) << 2;
            float4 t = *(const float4*)(kbase + (size_t)(kt * 64 + r) * 64 + c);
            uint4 u = make_uint4(f2tf(t.x), f2tf(t.y), f2tf(t.z), f2tf(t.w));
            *(uint4*)&KVs[r * ATT_ST + c] = u;
        }
        __syncthreads();

        float s[8][4];
        #pragma unroll
        for (int nt = 0; nt < 8; nt++)
            #pragma unroll
            for (int r = 0; r < 4; r++) s[nt][r] = 0.0f;
        #pragma unroll
        for (int ks = 0; ks < 8; ks++) {
            int kb = ks * 8;
            #pragma unroll
            for (int nt = 0; nt < 8; nt++) {
                uint32_t bfr[2];
                bfr[0] = KVs[(nt * 8 + gr) * ATT_ST + kb + gk];
                bfr[1] = KVs[(nt * 8 + gr) * ATT_ST + kb + gk + 4];
                MMA_TF32(s[nt], qf[ks], bfr);
            }
        }

        float rmax_lo = -1e30f, rmax_hi = -1e30f;
        #pragma unroll
        for (int nt = 0; nt < 8; nt++) {
            int2 mv = *(const int2*)(mbase + kt * 64 + nt * 8 + (gk << 1));
            if (mv.x == 0) { s[nt][0] = -1e9f; s[nt][2] = -1e9f; }
            if (mv.y == 0) { s[nt][1] = -1e9f; s[nt][3] = -1e9f; }
            rmax_lo = fmaxf(rmax_lo, fmaxf(s[nt][0], s[nt][1]));
            rmax_hi = fmaxf(rmax_hi, fmaxf(s[nt][2], s[nt][3]));
        }
        rmax_lo = fmaxf(rmax_lo, __shfl_xor_sync(0xffffffffu, rmax_lo, 1));
        rmax_lo = fmaxf(rmax_lo, __shfl_xor_sync(0xffffffffu, rmax_lo, 2));
        rmax_hi = fmaxf(rmax_hi, __shfl_xor_sync(0xffffffffu, rmax_hi, 1));
        rmax_hi = fmaxf(rmax_hi, __shfl_xor_sync(0xffffffffu, rmax_hi, 2));

        float nm_lo = fmaxf(m_lo, rmax_lo);
        float nm_hi = fmaxf(m_hi, rmax_hi);
        float corr_lo = __expf(m_lo - nm_lo);
        float corr_hi = __expf(m_hi - nm_hi);
        float rs_lo = 0.0f, rs_hi = 0.0f;
        #pragma unroll
        for (int nt = 0; nt < 8; nt++) {
            s[nt][0] = __expf(s[nt][0] - nm_lo);
            s[nt][1] = __expf(s[nt][1] - nm_lo);
            s[nt][2] = __expf(s[nt][2] - nm_hi);
            s[nt][3] = __expf(s[nt][3] - nm_hi);
            rs_lo += s[nt][0] + s[nt][1];
            rs_hi += s[nt][2] + s[nt][3];
        }
        rs_lo += __shfl_xor_sync(0xffffffffu, rs_lo, 1);
        rs_lo += __shfl_xor_sync(0xffffffffu, rs_lo, 2);
        rs_hi += __shfl_xor_sync(0xffffffffu, rs_hi, 1);
        rs_hi += __shfl_xor_sync(0xffffffffu, rs_hi, 2);
        l_lo = l_lo * corr_lo + rs_lo;  m_lo = nm_lo;
        l_hi = l_hi * corr_hi + rs_hi;  m_hi = nm_hi;
        #pragma unroll
        for (int nt = 0; nt < 8; nt++) {
            o[nt][0] *= corr_lo; o[nt][1] *= corr_lo;
            o[nt][2] *= corr_hi; o[nt][3] *= corr_hi;
        }

        #pragma unroll
        for (int nt = 0; nt < 8; nt++) {
            int c = nt * 8 + (gk << 1);
            *(uint2*)&Ps[(wm + gr) * ATT_ST + c]     = make_uint2(f2tf(s[nt][0]), f2tf(s[nt][1]));
            *(uint2*)&Ps[(wm + gr + 8) * ATT_ST + c] = make_uint2(f2tf(s[nt][2]), f2tf(s[nt][3]));
        }
        __syncthreads();

        #pragma unroll
        for (int i = 0; i < 8; i++) {
            int f = tid + i * 128;
            int r = f >> 4;
            int c = (f & 15) << 2;
            float4 t = *(const float4*)(vbase + (size_t)(kt * 64 + r) * 64 + c);
            KVs[(c + 0) * ATT_ST + r] = f2tf(t.x);
            KVs[(c + 1) * ATT_ST + r] = f2tf(t.y);
            KVs[(c + 2) * ATT_ST + r] = f2tf(t.z);
            KVs[(c + 3) * ATT_ST + r] = f2tf(t.w);
        }
        __syncthreads();

        #pragma unroll
        for (int ks = 0; ks < 8; ks++) {
            int kb = ks * 8;
            uint32_t af[4];
            af[0] = Ps[(wm + gr) * ATT_ST + kb + gk];
            af[1] = Ps[(wm + gr + 8) * ATT_ST + kb + gk];
            af[2] = Ps[(wm + gr) * ATT_ST + kb + gk + 4];
            af[3] = Ps[(wm + gr + 8) * ATT_ST + kb + gk + 4];
            #pragma unroll
            for (int nt = 0; nt < 8; nt++) {
                uint32_t bfr[2];
                bfr[0] = KVs[(nt * 8 + gr) * ATT_ST + kb + gk];
                bfr[1] = KVs[(nt * 8 + gr) * ATT_ST + kb + gk + 4];
                MMA_TF32(o[nt], af, bfr);
            }
        }
    }

    int h = bh & 15;
    float inv_lo = 1.0f / l_lo;
    float inv_hi = 1.0f / l_hi;
    size_t rbase = (size_t)(b * SS + qt * 64);
    #pragma unroll
    for (int nt = 0; nt < 8; nt++) {
        int c = h * 64 + nt * 8 + (gk << 1);
        *(float2*)(ctx + (rbase + wm + gr) * DD + c) =
            make_float2(o[nt][0] * inv_lo, o[nt][1] * inv_lo);
        *(float2*)(ctx + (rbase + wm + gr + 8) * DD + c) =
            make_float2(o[nt][2] * inv_hi, o[nt][3] * inv_hi);
    }
}

// ---------------- launch ----------------
extern "C" void kernel_launch(void* const* d_in, const int* in_sizes, int n_in,
                              void* d_out, int out_size) {
    const float* x    = (const float*)d_in[0];
    const int*   mask = (const int*)  d_in[1];
    const float* Wq   = (const float*)d_in[2];
    const float* bq   = (const float*)d_in[3];
    const float* Wk   = (const float*)d_in[4];
    const float* bk   = (const float*)d_in[5];
    const float* Wv   = (const float*)d_in[6];
    const float* bv   = (const float*)d_in[7];
    const float* Wo   = (const float*)d_in[8];
    const float* bo   = (const float*)d_in[9];
    const float* W1   = (const float*)d_in[10];
    const float* b1   = (const float*)d_in[11];
    const float* W2   = (const float*)d_in[12];
    const float* b2   = (const float*)d_in[13];
    const float* a1   = (const float*)d_in[14];
    const float* be1  = (const float*)d_in[15];
    const float* a2   = (const float*)d_in[16];
    const float* be2  = (const float*)d_in[17];
    float* out = (float*)d_out;

    float *xn = nullptr, *q = nullptr, *k = nullptr, *v = nullptr;
    float *ctx = nullptr, *x1 = nullptr, *h = nullptr;
    cudaGetSymbolAddress((void**)&xn,  g_xn);
    cudaGetSymbolAddress((void**)&q,   g_q);
    cudaGetSymbolAddress((void**)&k,   g_k);
    cudaGetSymbolAddress((void**)&v,   g_v);
    cudaGetSymbolAddress((void**)&ctx, g_ctx);
    cudaGetSymbolAddress((void**)&x1,  g_x1);
    cudaGetSymbolAddress((void**)&h,   g_h);

    // raise dynamic smem limit for the 2-stage GEMM kernels (idempotent, capture-safe)
    cudaFuncSetAttribute(gemm_tc<1>, cudaFuncAttributeMaxDynamicSharedMemorySize, GEMM_SMEM_BYTES);
    cudaFuncSetAttribute(gemm_tc<2>, cudaFuncAttributeMaxDynamicSharedMemorySize, GEMM_SMEM_BYTES);
    cudaFuncSetAttribute(gemm_qkv,   cudaFuncAttributeMaxDynamicSharedMemorySize, GEMM_SMEM_BYTES);

    dim3 blk(256);
    dim3 g_qkv(DD / 128, NROW / 128, 3);  // (8, 32, 3) fused QKV
    dim3 g_dxd(DD / 128, NROW / 128);     // (8, 32)
    dim3 g_ffn1(DFF / 128, NROW / 128);   // (32, 32)

    ln_kernel<<<NROW, blk>>>(x, a1, be1, xn);
    gemm_qkv<<<g_qkv, blk, GEMM_SMEM_BYTES>>>(xn, Wq, Wk, Wv, bq, bk, bv, q, k, v);
    attn_tc<<<dim3(SS / 64, BB * HH), 128>>>(q, k, v, mask, ctx);
    gemm_tc<1><<<g_dxd, blk, GEMM_SMEM_BYTES>>>(ctx, Wo, bo, x, x1, DD, DD);
    ln_kernel<<<NROW, blk>>>(x1, a2, be2, xn);
    gemm_tc<2><<<g_ffn1, blk, GEMM_SMEM_BYTES>>>(xn, W1, b1, nullptr, h, DFF, DD);
    gemm_tc<1><<<g_dxd, blk, GEMM_SMEM_BYTES>>>(h, W2, b2, x1, out, DD, DFF);
}

// round 12
// speedup vs baseline: 1.2974x; 1.2974x over previous
#include <cuda_runtime.h>
#include <math.h>
#include <stdint.h>

// Problem dims
#define BB 2
#define SS 2048
#define DD 1024
#define HH 16
#define DKK 64
#define DFF 4096
#define NROW 4096   // B*S

// ---------------- scratch (device globals; no allocation allowed) ----------------
__device__ float g_xn [NROW * DD];
__device__ float g_q  [NROW * DD];
__device__ float g_k  [NROW * DD];
__device__ float g_v  [NROW * DD];
__device__ float g_ctx[NROW * DD];
__device__ float g_x1 [NROW * DD];
__device__ float g_h  [NROW * DFF];
// tf32-rounded weight copies
__device__ float g_rwq[DD * DD];
__device__ float g_rwk[DD * DD];
__device__ float g_rwv[DD * DD];
__device__ float g_rwo[DD * DD];
__device__ float g_rw1[DD * DFF];
__device__ float g_rw2[DFF * DD];

// ---------------- helpers ----------------
__device__ __forceinline__ uint32_t f2tf(float f) {
    uint32_t u;
    asm("cvt.rna.tf32.f32 %0, %1;" : "=r"(u) : "f"(f));
    return u;
}
__device__ __forceinline__ uint32_t smem_u32(const void* p) {
    uint32_t a;
    asm("{ .reg .u64 t; cvta.to.shared.u64 t, %1; cvt.u32.u64 %0, t; }" : "=r"(a) : "l"(p));
    return a;
}

#define MMA_TF32(d, a, b) \
    asm volatile("mma.sync.aligned.m16n8k8.row.col.f32.tf32.tf32.f32 " \
                 "{%0,%1,%2,%3},{%4,%5,%6,%7},{%8,%9},{%0,%1,%2,%3};" \
                 : "+f"(d[0]), "+f"(d[1]), "+f"(d[2]), "+f"(d[3]) \
                 : "r"(a[0]), "r"(a[1]), "r"(a[2]), "r"(a[3]), "r"(b[0]), "r"(b[1]))

#define CP16(dst, src) \
    asm volatile("cp.async.cg.shared.global [%0], [%1], 16;" :: "r"(dst), "l"(src) : "memory")
#define CP_COMMIT() asm volatile("cp.async.commit_group;" ::: "memory")
#define CP_WAIT1()  asm volatile("cp.async.wait_group 1;" ::: "memory")

// ---------------- tf32 rounding copy (weights) ----------------
__global__ __launch_bounds__(256)
void round_tf32(const float* __restrict__ src, float* __restrict__ dst, int n4) {
    int i = blockIdx.x * 256 + threadIdx.x;
    if (i < n4) {
        float4 t = ((const float4*)src)[i];
        uint4 u = make_uint4(f2tf(t.x), f2tf(t.y), f2tf(t.z), f2tf(t.w));
        ((uint4*)dst)[i] = u;
    }
}

// ---------------- LayerNorm (unbiased std, eps on std); output tf32-rounded ----------------
__global__ __launch_bounds__(256)
void ln_kernel(const float* __restrict__ x, const float* __restrict__ alpha,
               const float* __restrict__ beta, float* __restrict__ y) {
    __shared__ float red[8];
    int row = blockIdx.x;
    int tid = threadIdx.x;
    const float* xr = x + (size_t)row * DD;
    float4 v = *(const float4*)(xr + tid * 4);
    float s = v.x + v.y + v.z + v.w;
    #pragma unroll
    for (int off = 16; off > 0; off >>= 1) s += __shfl_xor_sync(0xffffffffu, s, off);
    if ((tid & 31) == 0) red[tid >> 5] = s;
    __syncthreads();
    float tot = red[0] + red[1] + red[2] + red[3] + red[4] + red[5] + red[6] + red[7];
    float mean = tot * (1.0f / 1024.0f);
    float dx = v.x - mean, dy = v.y - mean, dz = v.z - mean, dw = v.w - mean;
    float sq = dx * dx + dy * dy + dz * dz + dw * dw;
    #pragma unroll
    for (int off = 16; off > 0; off >>= 1) sq += __shfl_xor_sync(0xffffffffu, sq, off);
    __syncthreads();
    if ((tid & 31) == 0) red[tid >> 5] = sq;
    __syncthreads();
    float var = (red[0] + red[1] + red[2] + red[3] + red[4] + red[5] + red[6] + red[7])
                * (1.0f / 1023.0f);
    float sc = alpha[0] / (sqrtf(var) + 1e-6f);
    float be = beta[0];
    uint4 o = make_uint4(f2tf(dx * sc + be), f2tf(dy * sc + be),
                         f2tf(dz * sc + be), f2tf(dw * sc + be));
    *(uint4*)(y + (size_t)row * DD + tid * 4) = o;
}

// ---------------- TF32 GEMM, 128x128 tile, kt=32, cp.async 3-stage ----------------
// Inputs A and Bm MUST be pre-rounded to tf32 values (stored as fp32 bits).
// EPI: 0 = bias + scatter to [B,H,S,DK]; 1 = bias + residual add; 2 = bias + ReLU + tf32-round
#define AS_STRIDE 36
#define BS_STRIDE 136
#define AS_BYTES (128 * AS_STRIDE * 4)   // 18432
#define BS_BYTES (32 * BS_STRIDE * 4)    // 17408
#define STG_BYTES (AS_BYTES + BS_BYTES)  // 35840
#define NSTAGE 3
#define GEMM_SMEM_BYTES (NSTAGE * STG_BYTES)  // 107520

template <int EPI>
__device__ __forceinline__
void gemm_body(const float* __restrict__ A, const float* __restrict__ Bm,
               const float* __restrict__ bias, const float* __restrict__ res,
               float* __restrict__ C, int N, int K, int brow, int bcol) {
    extern __shared__ char smc[];
    uint32_t smbase = smem_u32(smc);

    int tid  = threadIdx.x;
    int lane = tid & 31;
    int wid  = tid >> 5;
    int wm = (wid >> 2) * 64;
    int wn = (wid & 3) * 32;
    int gr = lane >> 2;
    int gk = lane & 3;

    const float* Abase = A + (size_t)brow * K;
    const float* Bbase = Bm + bcol;

    // per-thread chunk mapping (4 A chunks + 4 B chunks of 16B each per stage)
    int aRow[4], aCol[4], bRow[4], bCol[4];
    uint32_t aDst[4], bDst[4];
    #pragma unroll
    for (int i = 0; i < 4; i++) {
        int j = tid + i * 256;
        aRow[i] = j >> 3;  aCol[i] = (j & 7) << 2;
        bRow[i] = j >> 5;  bCol[i] = (j & 31) << 2;
        aDst[i] = (uint32_t)((aRow[i] * AS_STRIDE + aCol[i]) * 4);
        bDst[i] = (uint32_t)(AS_BYTES + (bRow[i] * BS_STRIDE + bCol[i]) * 4);
    }

    int ntiles = K >> 5;

    #define STAGE_CP(kt, s) do { \
        const float* _a = Abase + (kt) * 32; \
        const float* _b = Bbase + (size_t)((kt) * 32) * N; \
        uint32_t _sb = smbase + (uint32_t)((s) * STG_BYTES); \
        _Pragma("unroll") \
        for (int i = 0; i < 4; i++) { \
            CP16(_sb + aDst[i], _a + (size_t)aRow[i] * K + aCol[i]); \
            CP16(_sb + bDst[i], _b + (size_t)bRow[i] * N + bCol[i]); \
        } \
        CP_COMMIT(); \
    } while (0)

    STAGE_CP(0, 0);
    if (ntiles > 1) STAGE_CP(1, 1); else CP_COMMIT();

    float acc[4][4][4];
    #pragma unroll
    for (int mt = 0; mt < 4; mt++)
        #pragma unroll
        for (int nt = 0; nt < 4; nt++)
            #pragma unroll
            for (int r = 0; r < 4; r++) acc[mt][nt][r] = 0.0f;

    for (int kt = 0; kt < ntiles; kt++) {
        CP_WAIT1();
        __syncthreads();
        int s = kt % NSTAGE;
        const uint32_t* As = (const uint32_t*)(smc + (size_t)s * STG_BYTES);
        const uint32_t* Bs = (const uint32_t*)(smc + (size_t)s * STG_BYTES + AS_BYTES);
        #pragma unroll
        for (int k8 = 0; k8 < 4; k8++) {
            int kb = k8 * 8;
            uint32_t a[4][4], b[4][2];
            #pragma unroll
            for (int mt = 0; mt < 4; mt++) {
                int r = wm + mt * 16 + gr;
                a[mt][0] = As[r * AS_STRIDE + kb + gk];
                a[mt][1] = As[(r + 8) * AS_STRIDE + kb + gk];
                a[mt][2] = As[r * AS_STRIDE + kb + gk + 4];
                a[mt][3] = As[(r + 8) * AS_STRIDE + kb + gk + 4];
            }
            #pragma unroll
            for (int nt = 0; nt < 4; nt++) {
                int cn = wn + nt * 8 + gr;
                b[nt][0] = Bs[(kb + gk) * BS_STRIDE + cn];
                b[nt][1] = Bs[(kb + gk + 4) * BS_STRIDE + cn];
            }
            #pragma unroll
            for (int mt = 0; mt < 4; mt++)
                #pragma unroll
                for (int nt = 0; nt < 4; nt++)
                    MMA_TF32(acc[mt][nt], a[mt], b[nt]);
        }
        if (kt + 2 < ntiles) STAGE_CP(kt + 2, (kt + 2) % NSTAGE);
        else CP_COMMIT();   // keep group accounting uniform
    }

    // ---------------- epilogue ----------------
    #pragma unroll
    for (int mt = 0; mt < 4; mt++) {
        int r0 = brow + wm + mt * 16 + gr;
        int r1 = r0 + 8;
        #pragma unroll
        for (int nt = 0; nt < 4; nt++) {
            int c = bcol + wn + nt * 8 + (gk << 1);
            float2 bv = *(const float2*)(bias + c);
            float2 lo = make_float2(acc[mt][nt][0] + bv.x, acc[mt][nt][1] + bv.y);
            float2 hi = make_float2(acc[mt][nt][2] + bv.x, acc[mt][nt][3] + bv.y);
            if (EPI == 1) {
                float2 rl = *(const float2*)(res + (size_t)r0 * N + c);
                float2 rh = *(const float2*)(res + (size_t)r1 * N + c);
                lo.x += rl.x; lo.y += rl.y; hi.x += rh.x; hi.y += rh.y;
            }
            if (EPI == 2) {  // ReLU + round (output feeds next GEMM's A)
                lo.x = __uint_as_float(f2tf(fmaxf(lo.x, 0.0f)));
                lo.y = __uint_as_float(f2tf(fmaxf(lo.y, 0.0f)));
                hi.x = __uint_as_float(f2tf(fmaxf(hi.x, 0.0f)));
                hi.y = __uint_as_float(f2tf(fmaxf(hi.y, 0.0f)));
            }
            if (EPI == 0) {
                int h_ = c >> 6, dkc = c & 63;
                int b0_ = r0 >> 11, s0_ = r0 & 2047;
                int b1_ = r1 >> 11, s1_ = r1 & 2047;
                *(float2*)(C + ((((size_t)b0_ * HH + h_) * SS + s0_) << 6) + dkc) = lo;
                *(float2*)(C + ((((size_t)b1_ * HH + h_) * SS + s1_) << 6) + dkc) = hi;
            } else {
                *(float2*)(C + (size_t)r0 * N + c) = lo;
                *(float2*)(C + (size_t)r1 * N + c) = hi;
            }
        }
    }
    #undef STAGE_CP
}

template <int EPI>
__global__ __launch_bounds__(256, 2)
void gemm_tc(const float* __restrict__ A, const float* __restrict__ Bm,
             const float* __restrict__ bias, const float* __restrict__ res,
             float* __restrict__ C, int N, int K) {
    gemm_body<EPI>(A, Bm, bias, res, C, N, K, blockIdx.y * 128, blockIdx.x * 128);
}

__global__ __launch_bounds__(256, 2)
void gemm_qkv(const float* __restrict__ A,
              const float* __restrict__ W0, const float* __restrict__ W1q, const float* __restrict__ W2q,
              const float* __restrict__ c0, const float* __restrict__ c1, const float* __restrict__ c2,
              float* __restrict__ O0, float* __restrict__ O1, float* __restrict__ O2) {
    int z = blockIdx.z;
    const float* W = (z == 0) ? W0 : (z == 1) ? W1q : W2q;
    const float* bb = (z == 0) ? c0 : (z == 1) ? c1 : c2;
    float* O = (z == 0) ? O0 : (z == 1) ? O1 : O2;
    gemm_body<0>(A, W, bb, nullptr, O, DD, DD, blockIdx.y * 128, blockIdx.x * 128);
}

// ---------------- TF32 tensor-core flash attention (ctx output tf32-rounded) ----------------
#define ATT_ST 68

__global__ __launch_bounds__(128)
void attn_tc(const float* __restrict__ q, const float* __restrict__ k,
             const float* __restrict__ v, const int* __restrict__ mask,
             float* __restrict__ ctx) {
    __shared__ uint32_t KVs[64 * ATT_ST];
    __shared__ uint32_t Ps[64 * ATT_ST];

    int tid  = threadIdx.x;
    int lane = tid & 31;
    int wid  = tid >> 5;
    int gr   = lane >> 2;
    int gk   = lane & 3;
    int wm   = wid * 16;

    int bh = blockIdx.y;
    int qt = blockIdx.x;
    int b  = bh >> 4;
    const float* qbase = q + ((size_t)bh * SS + qt * 64) * DKK;
    const float* kbase = k + (size_t)bh * SS * DKK;
    const float* vbase = v + (size_t)bh * SS * DKK;
    const int*   mbase = mask + b * SS;

    uint32_t qf[8][4];
    #pragma unroll
    for (int ks = 0; ks < 8; ks++) {
        int kc = ks * 8 + gk;
        qf[ks][0] = f2tf(0.125f * qbase[(wm + gr) * 64 + kc]);
        qf[ks][1] = f2tf(0.125f * qbase[(wm + gr + 8) * 64 + kc]);
        qf[ks][2] = f2tf(0.125f * qbase[(wm + gr) * 64 + kc + 4]);
        qf[ks][3] = f2tf(0.125f * qbase[(wm + gr + 8) * 64 + kc + 4]);
    }

    float o[8][4];
    #pragma unroll
    for (int nt = 0; nt < 8; nt++)
        #pragma unroll
        for (int r = 0; r < 4; r++) o[nt][r] = 0.0f;
    float m_lo = -1e30f, m_hi = -1e30f, l_lo = 0.0f, l_hi = 0.0f;

    for (int kt = 0; kt < SS / 64; kt++) {
        __syncthreads();
        #pragma unroll
        for (int i = 0; i < 8; i++) {
            int f = tid + i * 128;
            int r = f >> 4;
            int c = (f & 15) << 2;
            float4 t = *(const float4*)(kbase + (size_t)(kt * 64 + r) * 64 + c);
            uint4 u = make_uint4(f2tf(t.x), f2tf(t.y), f2tf(t.z), f2tf(t.w));
            *(uint4*)&KVs[r * ATT_ST + c] = u;
        }
        __syncthreads();

        float s[8][4];
        #pragma unroll
        for (int nt = 0; nt < 8; nt++)
            #pragma unroll
            for (int r = 0; r < 4; r++) s[nt][r] = 0.0f;
        #pragma unroll
        for (int ks = 0; ks < 8; ks++) {
            int kb = ks * 8;
            #pragma unroll
            for (int nt = 0; nt < 8; nt++) {
                uint32_t bfr[2];
                bfr[0] = KVs[(nt * 8 + gr) * ATT_ST + kb + gk];
                bfr[1] = KVs[(nt * 8 + gr) * ATT_ST + kb + gk + 4];
                MMA_TF32(s[nt], qf[ks], bfr);
            }
        }

        float rmax_lo = -1e30f, rmax_hi = -1e30f;
        #pragma unroll
        for (int nt = 0; nt < 8; nt++) {
            int2 mv = *(const int2*)(mbase + kt * 64 + nt * 8 + (gk << 1));
            if (mv.x == 0) { s[nt][0] = -1e9f; s[nt][2] = -1e9f; }
            if (mv.y == 0) { s[nt][1] = -1e9f; s[nt][3] = -1e9f; }
            rmax_lo = fmaxf(rmax_lo, fmaxf(s[nt][0], s[nt][1]));
            rmax_hi = fmaxf(rmax_hi, fmaxf(s[nt][2], s[nt][3]));
        }
        rmax_lo = fmaxf(rmax_lo, __shfl_xor_sync(0xffffffffu, rmax_lo, 1));
        rmax_lo = fmaxf(rmax_lo, __shfl_xor_sync(0xffffffffu, rmax_lo, 2));
        rmax_hi = fmaxf(rmax_hi, __shfl_xor_sync(0xffffffffu, rmax_hi, 1));
        rmax_hi = fmaxf(rmax_hi, __shfl_xor_sync(0xffffffffu, rmax_hi, 2));

        float nm_lo = fmaxf(m_lo, rmax_lo);
        float nm_hi = fmaxf(m_hi, rmax_hi);
        float corr_lo = __expf(m_lo - nm_lo);
        float corr_hi = __expf(m_hi - nm_hi);
        float rs_lo = 0.0f, rs_hi = 0.0f;
        #pragma unroll
        for (int nt = 0; nt < 8; nt++) {
            s[nt][0] = __expf(s[nt][0] - nm_lo);
            s[nt][1] = __expf(s[nt][1] - nm_lo);
            s[nt][2] = __expf(s[nt][2] - nm_hi);
            s[nt][3] = __expf(s[nt][3] - nm_hi);
            rs_lo += s[nt][0] + s[nt][1];
            rs_hi += s[nt][2] + s[nt][3];
        }
        rs_lo += __shfl_xor_sync(0xffffffffu, rs_lo, 1);
        rs_lo += __shfl_xor_sync(0xffffffffu, rs_lo, 2);
        rs_hi += __shfl_xor_sync(0xffffffffu, rs_hi, 1);
        rs_hi += __shfl_xor_sync(0xffffffffu, rs_hi, 2);
        l_lo = l_lo * corr_lo + rs_lo;  m_lo = nm_lo;
        l_hi = l_hi * corr_hi + rs_hi;  m_hi = nm_hi;
        #pragma unroll
        for (int nt = 0; nt < 8; nt++) {
            o[nt][0] *= corr_lo; o[nt][1] *= corr_lo;
            o[nt][2] *= corr_hi; o[nt][3] *= corr_hi;
        }

        #pragma unroll
        for (int nt = 0; nt < 8; nt++) {
            int c = nt * 8 + (gk << 1);
            *(uint2*)&Ps[(wm + gr) * ATT_ST + c]     = make_uint2(f2tf(s[nt][0]), f2tf(s[nt][1]));
            *(uint2*)&Ps[(wm + gr + 8) * ATT_ST + c] = make_uint2(f2tf(s[nt][2]), f2tf(s[nt][3]));
        }
        __syncthreads();

        #pragma unroll
        for (int i = 0; i < 8; i++) {
            int f = tid + i * 128;
            int r = f >> 4;
            int c = (f & 15) << 2;
            float4 t = *(const float4*)(vbase + (size_t)(kt * 64 + r) * 64 + c);
            KVs[(c + 0) * ATT_ST + r] = f2tf(t.x);
            KVs[(c + 1) * ATT_ST + r] = f2tf(t.y);
            KVs[(c + 2) * ATT_ST + r] = f2tf(t.z);
            KVs[(c + 3) * ATT_ST + r] = f2tf(t.w);
        }
        __syncthreads();

        #pragma unroll
        for (int ks = 0; ks < 8; ks++) {
            int kb = ks * 8;
            uint32_t af[4];
            af[0] = Ps[(wm + gr) * ATT_ST + kb + gk];
            af[1] = Ps[(wm + gr + 8) * ATT_ST + kb + gk];
            af[2] = Ps[(wm + gr) * ATT_ST + kb + gk + 4];
            af[3] = Ps[(wm + gr + 8) * ATT_ST + kb + gk + 4];
            #pragma unroll
            for (int nt = 0; nt < 8; nt++) {
                uint32_t bfr[2];
                bfr[0] = KVs[(nt * 8 + gr) * ATT_ST + kb + gk];
                bfr[1] = KVs[(nt * 8 + gr) * ATT_ST + kb + gk + 4];
                MMA_TF32(o[nt], af, bfr);
            }
        }
    }

    // epilogue: divide by l, round to tf32 (ctx feeds O-proj GEMM A), write
    int h = bh & 15;
    float inv_lo = 1.0f / l_lo;
    float inv_hi = 1.0f / l_hi;
    size_t rbase = (size_t)(b * SS + qt * 64);
    #pragma unroll
    for (int nt = 0; nt < 8; nt++) {
        int c = h * 64 + nt * 8 + (gk << 1);
        uint2 lo = make_uint2(f2tf(o[nt][0] * inv_lo), f2tf(o[nt][1] * inv_lo));
        uint2 hi = make_uint2(f2tf(o[nt][2] * inv_hi), f2tf(o[nt][3] * inv_hi));
        *(uint2*)(ctx + (rbase + wm + gr) * DD + c) = lo;
        *(uint2*)(ctx + (rbase + wm + gr + 8) * DD + c) = hi;
    }
}

// ---------------- launch ----------------
extern "C" void kernel_launch(void* const* d_in, const int* in_sizes, int n_in,
                              void* d_out, int out_size) {
    const float* x    = (const float*)d_in[0];
    const int*   mask = (const int*)  d_in[1];
    const float* Wq   = (const float*)d_in[2];
    const float* bq   = (const float*)d_in[3];
    const float* Wk   = (const float*)d_in[4];
    const float* bk   = (const float*)d_in[5];
    const float* Wv   = (const float*)d_in[6];
    const float* bv   = (const float*)d_in[7];
    const float* Wo   = (const float*)d_in[8];
    const float* bo   = (const float*)d_in[9];
    const float* W1   = (const float*)d_in[10];
    const float* b1   = (const float*)d_in[11];
    const float* W2   = (const float*)d_in[12];
    const float* b2   = (const float*)d_in[13];
    const float* a1   = (const float*)d_in[14];
    const float* be1  = (const float*)d_in[15];
    const float* a2   = (const float*)d_in[16];
    const float* be2  = (const float*)d_in[17];
    float* out = (float*)d_out;

    float *xn, *q, *k, *v, *ctx, *x1, *h;
    float *rwq, *rwk, *rwv, *rwo, *rw1, *rw2;
    cudaGetSymbolAddress((void**)&xn,  g_xn);
    cudaGetSymbolAddress((void**)&q,   g_q);
    cudaGetSymbolAddress((void**)&k,   g_k);
    cudaGetSymbolAddress((void**)&v,   g_v);
    cudaGetSymbolAddress((void**)&ctx, g_ctx);
    cudaGetSymbolAddress((void**)&x1,  g_x1);
    cudaGetSymbolAddress((void**)&h,   g_h);
    cudaGetSymbolAddress((void**)&rwq, g_rwq);
    cudaGetSymbolAddress((void**)&rwk, g_rwk);
    cudaGetSymbolAddress((void**)&rwv, g_rwv);
    cudaGetSymbolAddress((void**)&rwo, g_rwo);
    cudaGetSymbolAddress((void**)&rw1, g_rw1);
    cudaGetSymbolAddress((void**)&rw2, g_rw2);

    cudaFuncSetAttribute(gemm_tc<1>, cudaFuncAttributeMaxDynamicSharedMemorySize, GEMM_SMEM_BYTES);
    cudaFuncSetAttribute(gemm_tc<2>, cudaFuncAttributeMaxDynamicSharedMemorySize, GEMM_SMEM_BYTES);
    cudaFuncSetAttribute(gemm_qkv,   cudaFuncAttributeMaxDynamicSharedMemorySize, GEMM_SMEM_BYTES);

    dim3 g_qkv(DD / 128, NROW / 128, 3);
    dim3 g_dxd(DD / 128, NROW / 128);
    dim3 g_ffn1(DFF / 128, NROW / 128);
    int n4_dd  = DD * DD / 4;    // 262144
    int n4_dff = DD * DFF / 4;   // 1048576

    // pre-round weights to tf32 (values stored as fp32)
    round_tf32<<<(n4_dd  + 255) / 256, 256>>>(Wq, rwq, n4_dd);
    round_tf32<<<(n4_dd  + 255) / 256, 256>>>(Wk, rwk, n4_dd);
    round_tf32<<<(n4_dd  + 255) / 256, 256>>>(Wv, rwv, n4_dd);
    round_tf32<<<(n4_dd  + 255) / 256, 256>>>(Wo, rwo, n4_dd);
    round_tf32<<<(n4_dff + 255) / 256, 256>>>(W1, rw1, n4_dff);
    round_tf32<<<(n4_dff + 255) / 256, 256>>>(W2, rw2, n4_dff);

    ln_kernel<<<NROW, 256>>>(x, a1, be1, xn);
    gemm_qkv<<<g_qkv, 256, GEMM_SMEM_BYTES>>>(xn, rwq, rwk, rwv, bq, bk, bv, q, k, v);
    attn_tc<<<dim3(SS / 64, BB * HH), 128>>>(q, k, v, mask, ctx);
    gemm_tc<1><<<g_dxd, 256, GEMM_SMEM_BYTES>>>(ctx, rwo, bo, x, x1, DD, DD);
    ln_kernel<<<NROW, 256>>>(x1, a2, be2, xn);
    gemm_tc<2><<<g_ffn1, 256, GEMM_SMEM_BYTES>>>(xn, rw1, b1, nullptr, h, DFF, DD);
    gemm_tc<1><<<g_dxd, 256, GEMM_SMEM_BYTES>>>(h, rw2, b2, x1, out, DD, DFF);
}